// round 6
// baseline (speedup 1.0000x reference)
#include <cuda_runtime.h>
#include <cstdint>

// Depthwise causal FIR conv1d, K=31, fp32.
// x: (8, 4096, 2048) channel-last.  w: (2048, 31).  y like x.
//
// Round-6: occupancy-first streaming kernel.
//  - thread = channel pair (float2), TT=128 outputs, CHUNK=8, rolled chunk loop
//  - gmem -> 6-batch smem ring via predicated cp.async (zero-fill handles the
//    causal left pad and the right edge)
//  - smem -> 10-slot sliding register window (static mod-10 naming, LDS.64)
//  - taps in registers (62), FFMA2 math (fma.rn.f32x2)
//  - regs ~118 (launch_bounds cap 128) -> 8 blocks = 16 warps/SM

#define BB 8
#define LL 4096
#define CPAIR 1024
#define KK 31
#define CHUNK 8
#define TT 128
#define NCHUNK 16
#define THREADS 64
#define RING_OFF 48              // ring rows (offsets), 6 batches of 8
#define WIN 10                   // sliding register window slots

__device__ __forceinline__ float2 ffma2(float2 a, float2 b, float2 c) {
    float2 d;
    asm("fma.rn.f32x2 %0, %1, %2, %3;"
        : "=l"(*reinterpret_cast<unsigned long long*>(&d))
        : "l"(*reinterpret_cast<const unsigned long long*>(&a)),
          "l"(*reinterpret_cast<const unsigned long long*>(&b)),
          "l"(*reinterpret_cast<const unsigned long long*>(&c)));
    return d;
}

// cp.async with runtime src-size: sz=8 copies, sz=0 zero-fills dst (no gmem read).
__device__ __forceinline__ void cp_async8(uint32_t saddr, const void* gptr, uint32_t sz) {
    asm volatile("cp.async.ca.shared.global [%0], [%1], 8, %2;"
                 :: "r"(saddr), "l"(gptr), "r"(sz) : "memory");
}
__device__ __forceinline__ void cp_commit() {
    asm volatile("cp.async.commit_group;" ::: "memory");
}
__device__ __forceinline__ void cp_wait1() {
    asm volatile("cp.async.wait_group 1;" ::: "memory");
}

__global__ __launch_bounds__(THREADS, 8)
void _DepthwiseFIRConv1d_kernel(const float* __restrict__ x,
                                const float* __restrict__ w,
                                float* __restrict__ y) {
    // ring[row][tid]: row = offset mod 48; per-thread column -> conflict-free
    __shared__ float2 ring[RING_OFF][THREADS];           // 24 KB

    const int tid = threadIdx.x;
    const int cp  = blockIdx.x * THREADS + tid;          // channel pair 0..1023
    const int l0  = blockIdx.y * TT;
    const int b   = blockIdx.z;

    const float2* xb = reinterpret_cast<const float2*>(x) + (size_t)b * LL * CPAIR + cp;
    float2*       yb = reinterpret_cast<float2*>(y) + ((size_t)b * LL + l0) * CPAIR + cp;
    const int base = l0 - (KK - 1);

    const float2* ring_col = &ring[0][tid];

    // Taps -> registers (reused for all 128 outputs).
    const float* w0 = w + (2 * cp) * KK;
    float2 wt[KK];
#pragma unroll
    for (int t = 0; t < KK; t++)
        wt[t] = make_float2(__ldg(w0 + t), __ldg(w0 + KK + t));

    // Prologue: batches 0..4 (offsets 0..39). l<0 -> zero-fill (causal pad).
#pragma unroll
    for (int m = 0; m < 5; m++) {
#pragma unroll
        for (int i = 0; i < CHUNK; i++) {
            const int off = 8 * m + i;
            const int l = base + off;                    // < LL always here
            const uint32_t sz = (l >= 0) ? 8u : 0u;
            const int lc = (l >= 0) ? l : 0;
            cp_async8((uint32_t)__cvta_generic_to_shared(&ring[off][tid]),
                      xb + (size_t)lc * CPAIR, sz);
        }
        cp_commit();
    }

    int ld_row = 0;          // ring row of offset 8c
    int pf_row = 40;         // ring row of offset 8(c+5)
    int pf_l   = l0 + 10;    // l of first element of batch c+5 (= base + 8c + 40)

#pragma unroll 1
    for (int c = 0; c < NCHUNK; c++) {
        // Issue batch c+5 (batches 5..19). Right-edge guard via zero-fill.
        if (c < NCHUNK - 1) {
#pragma unroll
            for (int i = 0; i < CHUNK; i++) {
                const int l = pf_l + i;                  // >= 0 always
                const uint32_t sz = (l < LL) ? 8u : 0u;
                const int lc = (l < LL) ? l : (LL - 1);
                cp_async8((uint32_t)__cvta_generic_to_shared(&ring[pf_row + i][tid]),
                          xb + (size_t)lc * CPAIR, sz);
            }
        }
        cp_commit();
        cp_wait1();                                      // batches <= c+4 resident

        // Sliding window compute: offsets 8c .. 8c+37 streamed via LDS.64.
        int r = ld_row;
        float2 buf[WIN];
#pragma unroll
        for (int k = 0; k < 9; k++) {                    // offsets 8c .. 8c+8
            buf[k] = ring_col[r * THREADS];
            r++; if (r == RING_OFF) r = 0;
        }

        float2 acc[CHUNK];
#pragma unroll
        for (int j = 0; j < CHUNK; j++) acc[j] = make_float2(0.0f, 0.0f);

#pragma unroll
        for (int t = 0; t < KK; t++) {
            if (t <= 28) {                               // load offset 8c+t+9
                buf[(t + 9) % WIN] = ring_col[r * THREADS];
                r++; if (r == RING_OFF) r = 0;
            }
#pragma unroll
            for (int j = 0; j < CHUNK; j++)
                acc[j] = ffma2(wt[t], buf[(t + j) % WIN], acc[j]);
        }

#pragma unroll
        for (int j = 0; j < CHUNK; j++)
            yb[(size_t)j * CPAIR] = acc[j];
        yb += (size_t)CHUNK * CPAIR;

        ld_row += 8; if (ld_row >= RING_OFF) ld_row -= RING_OFF;
        pf_row += 8; if (pf_row >= RING_OFF) pf_row -= RING_OFF;
        pf_l   += 8;
    }
}

extern "C" void kernel_launch(void* const* d_in, const int* in_sizes, int n_in,
                              void* d_out, int out_size) {
    const float* x = (const float*)d_in[0];   // (8, 4096, 16, 128)
    const float* w = (const float*)d_in[1];   // (16, 128, 31)
    float* yv = (float*)d_out;

    dim3 grid(CPAIR / THREADS, LL / TT, BB);  // (16, 32, 8) = 4096 blocks
    _DepthwiseFIRConv1d_kernel<<<grid, THREADS>>>(x, w, yv);
}